// round 14
// baseline (speedup 1.0000x reference)
#include <cuda_runtime.h>

// Problem constants (fixed by the dataset)
static constexpr int NN  = 50000;   // nodes
static constexpr int NE  = 400000;  // edges
static constexpr int F0  = 128;     // input features
static constexpr int F1  = 256;     // hidden 1
static constexpr int F2  = 784;     // hidden 2
static constexpr int NC  = 10;      // classes

// ---------------- device scratch (static, allocation-free) ----------------
__device__ int   g_e64;
__device__ int   g_src32[NE];
__device__ int   g_dst32[NE];
__device__ float g_dinv[NN];
__device__ float g_norm[NE];
__device__ float g_aggx[(size_t)NN * F0];
__device__ float g_l1  [(size_t)NN * F1];
__device__ float g_aggh[(size_t)NN * F1];
__device__ float g_logits[(size_t)NN * NC];

// ---------------- dtype detection + fused index conversion/degree ----------------
__global__ void k_detect(const unsigned int* __restrict__ ei32) {
    if (threadIdx.x == 0 && blockIdx.x == 0) {
        int all0 = 1;
        #pragma unroll 1
        for (int i = 0; i < 64; i++)
            if (ei32[2 * i + 1] != 0u) { all0 = 0; break; }
        g_e64 = all0;
    }
}

__device__ __forceinline__ int edge_idx(const void* ei, int half, int e) {
    if (g_e64) return (int)((const long long*)ei)[(size_t)half * NE + e];
    return ((const int*)ei)[(size_t)half * NE + e];
}

__global__ void k_deg_init() {
    int i = blockIdx.x * blockDim.x + threadIdx.x;
    if (i < NN) g_dinv[i] = 1.0f;
}

__global__ void k_convert_deg(const void* __restrict__ ei) {
    int e = blockIdx.x * blockDim.x + threadIdx.x;
    if (e < NE) {
        int s = edge_idx(ei, 0, e);
        int d = edge_idx(ei, 1, e);
        g_src32[e] = s;
        g_dst32[e] = d;
        atomicAdd(&g_dinv[d], 1.0f);
    }
}

__global__ void k_dinv() {
    int i = blockIdx.x * blockDim.x + threadIdx.x;
    if (i < NN) g_dinv[i] = rsqrtf(g_dinv[i]);
}

__global__ void k_norm() {
    int e = blockIdx.x * blockDim.x + threadIdx.x;
    if (e < NE) g_norm[e] = g_dinv[g_src32[e]] * g_dinv[g_dst32[e]];
}

// ---------------- aggregation init: agg = h * self_norm ----------------
template <int LAYER>
__global__ void k_agg_init(const float* __restrict__ hparam, int F4, int total4) {
    const float* __restrict__ h = (LAYER == 1) ? hparam : g_l1;
    float* __restrict__ agg = (LAYER == 1) ? g_aggx : g_aggh;

    int idx = blockIdx.x * blockDim.x + threadIdx.x;
    if (idx >= total4) return;
    int node = idx / F4;
    float sn = g_dinv[node];
    sn *= sn;
    float4 v = *(const float4*)(h + (size_t)idx * 4);
    v.x *= sn; v.y *= sn; v.z *= sn; v.w *= sn;
    *(float4*)(agg + (size_t)idx * 4) = v;
}

// ---------------- edge scatter: agg[dst] += h[src] * norm ----------------
template <int LAYER>
__global__ void k_scatter(const float* __restrict__ hparam, int F4, long long total) {
    const float* __restrict__ h = (LAYER == 1) ? hparam : g_l1;
    float* __restrict__ agg = (LAYER == 1) ? g_aggx : g_aggh;

    long long idx = (long long)blockIdx.x * blockDim.x + threadIdx.x;
    if (idx >= total) return;
    int e = (int)(idx / F4);
    int q = (int)(idx - (long long)e * F4);
    int s = g_src32[e];
    int d = g_dst32[e];
    float w = g_norm[e];
    float4 v = *(const float4*)(h + (size_t)s * (F4 * 4) + q * 4);
    float* o = agg + (size_t)d * (F4 * 4) + q * 4;
    asm volatile("red.global.add.v4.f32 [%0], {%1,%2,%3,%4};"
                 :: "l"(o), "f"(v.x * w), "f"(v.y * w), "f"(v.z * w), "f"(v.w * w)
                 : "memory");
}

// ---------------- bf16 split / mma / ldmatrix helpers ----------------
__device__ __forceinline__ unsigned bf16pack(float e0, float e1) {
    unsigned r;
    asm("cvt.rn.bf16x2.f32 %0, %1, %2;" : "=r"(r) : "f"(e1), "f"(e0));
    return r;
}

__device__ __forceinline__ void bf16split(float e0, float e1, unsigned& h, unsigned& l) {
    h = bf16pack(e0, e1);
    float f0 = __uint_as_float(h << 16);
    float f1 = __uint_as_float(h & 0xFFFF0000u);
    l = bf16pack(e0 - f0, e1 - f1);
}

__device__ __forceinline__ void mma_bf16(float* d, const unsigned* a, const unsigned* b) {
    asm volatile(
        "mma.sync.aligned.m16n8k16.row.col.f32.bf16.bf16.f32 "
        "{%0,%1,%2,%3}, {%4,%5,%6,%7}, {%8,%9}, {%0,%1,%2,%3};"
        : "+f"(d[0]), "+f"(d[1]), "+f"(d[2]), "+f"(d[3])
        : "r"(a[0]), "r"(a[1]), "r"(a[2]), "r"(a[3]), "r"(b[0]), "r"(b[1]));
}

__device__ __forceinline__ void ldsm_x4(unsigned* r, unsigned addr) {
    asm volatile("ldmatrix.sync.aligned.m8n8.x4.shared.b16 {%0,%1,%2,%3}, [%4];"
                 : "=r"(r[0]), "=r"(r[1]), "=r"(r[2]), "=r"(r[3]) : "r"(addr));
}

// ---------------- tensor-core GEMM (3xBF16, ldmatrix, BK=32) ----------------
// LAYER==1: g_l1 = relu(g_aggx @ W1 + b1).                     M=NN, N=F1, K=F0
// LAYER==2: relu(g_aggh @ W2 + b2) @ Wc -> atomic g_logits.    M=NN, N=F2, K=F1
// BM=128, BN=64, BK=32; 256 threads = 8 warps (4M x 2N); warp tile 32x32.
// A smem: bf16x2 pairs [row][pair], stride 20 (conflict-free ldmatrix rows).
// B smem: n-major bf16x2 pairs [n][pair], stride 20.
template <int LAYER>
__global__ __launch_bounds__(256) void gemm_mma(const float* __restrict__ B,
                                                const float* __restrict__ bias,
                                                const float* __restrict__ Wc,
                                                int M, int N, int K) {
    const float* __restrict__ A = (LAYER == 1) ? g_aggx : g_aggh;

    constexpr int BM = 128, BN = 64, BK = 32;
    constexpr int PSTR = 20;            // pair-word stride (16 used + 4 pad)

    __shared__ __align__(16) unsigned As_h[BM][PSTR];
    __shared__ __align__(16) unsigned As_l[BM][PSTR];
    __shared__ __align__(16) unsigned Bs_h[BN][PSTR];
    __shared__ __align__(16) unsigned Bs_l[BN][PSTR];
    __shared__ float sWc[(LAYER == 2) ? BN * NC : 1];

    const int tid  = threadIdx.x;
    const int bm   = blockIdx.x * BM;
    const int bn   = blockIdx.y * BN;
    const int warp = tid >> 5;
    const int lane = tid & 31;
    const int wm   = (warp & 3) * 32;
    const int wn   = (warp >> 2) * 32;
    const int qr   = lane >> 2;
    const int qc   = lane & 3;

    // ---- staging maps ----
    const int ar  = tid >> 1;           // A row 0..127
    const int ah2 = tid & 1;            // A k-half {0,1}: pairs ah2*8..ah2*8+7
    const int bpk = tid & 15;           // B pair 0..15
    const int bng = (tid >> 4) * 4;     // B n base 0..60
    const bool arv = (bm + ar) < M;
    const bool bnv = (bn + bng) < N;    // N%4==0 -> all-or-nothing per float4

    if (LAYER == 2) {
        for (int i = tid; i < BN * NC; i += 256) {
            int row = bn + i / NC;
            sWc[i] = (row < F2) ? Wc[(size_t)row * NC + (i % NC)] : 0.f;
        }
    }

    // ---- ldmatrix smem addresses (u32) ----
    const unsigned uAs_h = (unsigned)__cvta_generic_to_shared(&As_h[0][0]);
    const unsigned uAs_l = (unsigned)__cvta_generic_to_shared(&As_l[0][0]);
    const unsigned uBs_h = (unsigned)__cvta_generic_to_shared(&Bs_h[0][0]);
    const unsigned uBs_l = (unsigned)__cvta_generic_to_shared(&Bs_l[0][0]);
    // A: lane -> row wm + mt*16 + (l&7) + ((l>>3)&1)*8, pair c*8 + ((l>>4)&1)*4
    const int a_row_off = (lane & 7) + ((lane >> 3) & 1) * 8;
    const int a_pc_off  = ((lane >> 4) & 1) * 4;
    // B: lane -> n wn + (2p + (l>>4))*8 + (l&7), pair c*8 + ((l>>3)&1)*4
    const int b_n_off   = ((lane >> 4) & 1) * 8 + (lane & 7);
    const int b_pc_off  = ((lane >> 3) & 1) * 4;

    float acc[2][4][4] = {};

    // ---- prefetch stage 0 ----
    float4 pa[4];
    float4 pb0 = make_float4(0.f, 0.f, 0.f, 0.f);
    float4 pb1 = make_float4(0.f, 0.f, 0.f, 0.f);
    #pragma unroll
    for (int i = 0; i < 4; i++) pa[i] = make_float4(0.f, 0.f, 0.f, 0.f);
    if (arv) {
        const float* ap = A + (size_t)(bm + ar) * K + ah2 * 16;
        #pragma unroll
        for (int i = 0; i < 4; i++) pa[i] = *(const float4*)(ap + i * 4);
    }
    if (bnv) {
        pb0 = *(const float4*)(B + (size_t)(2 * bpk    ) * N + bn + bng);
        pb1 = *(const float4*)(B + (size_t)(2 * bpk + 1) * N + bn + bng);
    }

    for (int k0 = 0; k0 < K; k0 += BK) {
        // ---- convert + store prefetched stage ----
        {
            const int pc = ah2 * 8;
            unsigned h[8], l[8];
            #pragma unroll
            for (int i = 0; i < 4; i++) {
                bf16split(pa[i].x, pa[i].y, h[2 * i],     l[2 * i]);
                bf16split(pa[i].z, pa[i].w, h[2 * i + 1], l[2 * i + 1]);
            }
            *(uint4*)&As_h[ar][pc]     = make_uint4(h[0], h[1], h[2], h[3]);
            *(uint4*)&As_h[ar][pc + 4] = make_uint4(h[4], h[5], h[6], h[7]);
            *(uint4*)&As_l[ar][pc]     = make_uint4(l[0], l[1], l[2], l[3]);
            *(uint4*)&As_l[ar][pc + 4] = make_uint4(l[4], l[5], l[6], l[7]);

            float be[4] = {pb0.x, pb0.y, pb0.z, pb0.w};
            float bo[4] = {pb1.x, pb1.y, pb1.z, pb1.w};
            #pragma unroll
            for (int j = 0; j < 4; j++) {
                unsigned bh, bl;
                bf16split(be[j], bo[j], bh, bl);
                Bs_h[bng + j][bpk] = bh;
                Bs_l[bng + j][bpk] = bl;
            }
        }
        __syncthreads();

        // ---- prefetch next stage ----
        const int kn = k0 + BK;
        if (kn < K) {
            if (arv) {
                const float* ap = A + (size_t)(bm + ar) * K + kn + ah2 * 16;
                #pragma unroll
                for (int i = 0; i < 4; i++) pa[i] = *(const float4*)(ap + i * 4);
            }
            if (bnv) {
                pb0 = *(const float4*)(B + (size_t)(kn + 2 * bpk    ) * N + bn + bng);
                pb1 = *(const float4*)(B + (size_t)(kn + 2 * bpk + 1) * N + bn + bng);
            }
        }

        // ---- two k16 chunks of MMAs ----
        #pragma unroll
        for (int c = 0; c < 2; c++) {
            unsigned ah[2][4], al[2][4];
            #pragma unroll
            for (int mt = 0; mt < 2; mt++) {
                unsigned off = ((wm + mt * 16 + a_row_off) * PSTR + c * 8 + a_pc_off) * 4;
                ldsm_x4(ah[mt], uAs_h + off);
                ldsm_x4(al[mt], uAs_l + off);
            }
            unsigned bh[4][2], bl[4][2];
            #pragma unroll
            for (int p = 0; p < 2; p++) {
                unsigned off = ((wn + p * 16 + b_n_off) * PSTR + c * 8 + b_pc_off) * 4;
                unsigned rh[4], rl[4];
                ldsm_x4(rh, uBs_h + off);
                ldsm_x4(rl, uBs_l + off);
                bh[2 * p][0] = rh[0]; bh[2 * p][1] = rh[1];
                bh[2 * p + 1][0] = rh[2]; bh[2 * p + 1][1] = rh[3];
                bl[2 * p][0] = rl[0]; bl[2 * p][1] = rl[1];
                bl[2 * p + 1][0] = rl[2]; bl[2 * p + 1][1] = rl[3];
            }
            #pragma unroll
            for (int mt = 0; mt < 2; mt++)
                #pragma unroll
                for (int nt = 0; nt < 4; nt++) {
                    mma_bf16(acc[mt][nt], ah[mt], bh[nt]);
                    mma_bf16(acc[mt][nt], ah[mt], bl[nt]);
                    mma_bf16(acc[mt][nt], al[mt], bh[nt]);
                }
        }
        __syncthreads();
    }

    if (LAYER == 1) {
        #pragma unroll
        for (int mt = 0; mt < 2; mt++) {
            const int r0 = bm + wm + mt * 16 + qr;
            #pragma unroll
            for (int nt = 0; nt < 4; nt++) {
                const int col = bn + wn + nt * 8 + qc * 2;
                if (col < N) {
                    float2 bv = *(const float2*)(bias + col);
                    float v0 = fmaxf(acc[mt][nt][0] + bv.x, 0.f);
                    float v1 = fmaxf(acc[mt][nt][1] + bv.y, 0.f);
                    float v2 = fmaxf(acc[mt][nt][2] + bv.x, 0.f);
                    float v3 = fmaxf(acc[mt][nt][3] + bv.y, 0.f);
                    if (r0 < M)
                        *(float2*)(g_l1 + (size_t)r0 * N + col) = make_float2(v0, v1);
                    if (r0 + 8 < M)
                        *(float2*)(g_l1 + (size_t)(r0 + 8) * N + col) = make_float2(v2, v3);
                }
            }
        }
    } else {
        // ---- fused classifier: partial logits ----
        float plog[4][NC];
        #pragma unroll
        for (int r = 0; r < 4; r++)
            #pragma unroll
            for (int c = 0; c < NC; c++) plog[r][c] = 0.f;

        #pragma unroll
        for (int mt = 0; mt < 2; mt++) {
            #pragma unroll
            for (int nt = 0; nt < 4; nt++) {
                const int col = bn + wn + nt * 8 + qc * 2;
                if (col < N) {
                    float2 bv = *(const float2*)(bias + col);
                    float v0 = fmaxf(acc[mt][nt][0] + bv.x, 0.f);
                    float v1 = fmaxf(acc[mt][nt][1] + bv.y, 0.f);
                    float v2 = fmaxf(acc[mt][nt][2] + bv.x, 0.f);
                    float v3 = fmaxf(acc[mt][nt][3] + bv.y, 0.f);
                    const float* w0 = &sWc[(col - bn) * NC];
                    const float* w1 = w0 + NC;
                    #pragma unroll
                    for (int c = 0; c < NC; c++) {
                        plog[mt * 2 + 0][c] += v0 * w0[c] + v1 * w1[c];
                        plog[mt * 2 + 1][c] += v2 * w0[c] + v3 * w1[c];
                    }
                }
            }
        }
        #pragma unroll
        for (int off = 1; off <= 2; off <<= 1)
            #pragma unroll
            for (int r = 0; r < 4; r++)
                #pragma unroll
                for (int c = 0; c < NC; c++)
                    plog[r][c] += __shfl_xor_sync(0xFFFFFFFFu, plog[r][c], off);

        if (qc == 0) {
            #pragma unroll
            for (int mt = 0; mt < 2; mt++) {
                const int r0 = bm + wm + mt * 16 + qr;
                if (r0 < M)
                    #pragma unroll
                    for (int c = 0; c < NC; c++)
                        atomicAdd(&g_logits[(size_t)r0 * NC + c], plog[mt * 2][c]);
                if (r0 + 8 < M)
                    #pragma unroll
                    for (int c = 0; c < NC; c++)
                        atomicAdd(&g_logits[(size_t)(r0 + 8) * NC + c], plog[mt * 2 + 1][c]);
            }
        }
    }
}

// ---------------- logits init (bc) + final log_softmax ----------------
__global__ void k_logits_init(const float* __restrict__ bc) {
    int i = blockIdx.x * blockDim.x + threadIdx.x;
    if (i < NN * NC) g_logits[i] = bc[i % NC];
}

__global__ void k_logsoftmax(float* __restrict__ out) {
    int n = blockIdx.x * blockDim.x + threadIdx.x;
    if (n >= NN) return;
    float l[NC];
    float m = -1e30f;
    #pragma unroll
    for (int c = 0; c < NC; c++) {
        l[c] = g_logits[(size_t)n * NC + c];
        m = fmaxf(m, l[c]);
    }
    float s = 0.f;
    #pragma unroll
    for (int c = 0; c < NC; c++) s += expf(l[c] - m);
    float ls = m + logf(s);
    #pragma unroll
    for (int c = 0; c < NC; c++)
        out[(size_t)n * NC + c] = l[c] - ls;
}

// ---------------- launch ----------------
extern "C" void kernel_launch(void* const* d_in, const int* in_sizes, int n_in,
                              void* d_out, int out_size) {
    const float* x   = (const float*)d_in[0];
    const void*  ei  = d_in[1];
    const float* W1  = (const float*)d_in[2];
    const float* b1  = (const float*)d_in[3];
    const float* W2  = (const float*)d_in[4];
    const float* b2  = (const float*)d_in[5];
    const float* Wc  = (const float*)d_in[6];
    const float* bc  = (const float*)d_in[7];
    float*       out = (float*)d_out;

    const int T = 256;

    k_detect<<<1, 32>>>((const unsigned int*)ei);
    k_deg_init<<<(NN + T - 1) / T, T>>>();
    k_convert_deg<<<(NE + T - 1) / T, T>>>(ei);
    k_dinv<<<(NN + T - 1) / T, T>>>();
    k_norm<<<(NE + T - 1) / T, T>>>();

    // aggx = S x
    {
        int total4 = NN * (F0 / 4);
        k_agg_init<1><<<(total4 + T - 1) / T, T>>>(x, F0 / 4, total4);
        long long tot = (long long)NE * (F0 / 4);
        k_scatter<1><<<(unsigned)((tot + T - 1) / T), T>>>(x, F0 / 4, tot);
    }

    // l1 = relu(aggx @ W1 + b1)
    gemm_mma<1><<<dim3((NN + 127) / 128, (F1 + 63) / 64), T>>>(W1, b1, nullptr, NN, F1, F0);

    // aggh = S l1
    {
        int total4 = NN * (F1 / 4);
        k_agg_init<2><<<(total4 + T - 1) / T, T>>>(nullptr, F1 / 4, total4);
        long long tot = (long long)NE * (F1 / 4);
        k_scatter<2><<<(unsigned)((tot + T - 1) / T), T>>>(nullptr, F1 / 4, tot);
    }

    // logits = bc; GEMM2 accumulates relu(aggh@W2+b2)@Wc atomically
    k_logits_init<<<(NN * NC + T - 1) / T, T>>>(bc);
    gemm_mma<2><<<dim3((NN + 127) / 128, (F2 + 63) / 64), T>>>(W2, b2, Wc, NN, F2, F1);

    k_logsoftmax<<<(NN + T - 1) / T, T>>>(out);
}

// round 17
// speedup vs baseline: 1.2299x; 1.2299x over previous
#include <cuda_runtime.h>

// Problem constants (fixed by the dataset)
static constexpr int NN  = 50000;   // nodes
static constexpr int NE  = 400000;  // edges
static constexpr int F0  = 128;     // input features
static constexpr int F1  = 256;     // hidden 1
static constexpr int F2  = 784;     // hidden 2
static constexpr int NC  = 10;      // classes

// ---------------- device scratch (static, allocation-free) ----------------
__device__ int   g_e64;
__device__ int   g_src32[NE];
__device__ int   g_dst32[NE];
__device__ float g_dinv[NN];                 // deg accumulator -> deg^-1/2
__device__ int   g_rowptr[NN + 1];           // CSR row pointers (by dst)
__device__ int   g_cursor[NN];               // bucket-fill cursors
__device__ int2  g_epack[NE];                // {src, norm-as-int} sorted by dst
__device__ float g_aggx[(size_t)NN * F0];
__device__ float g_l1  [(size_t)NN * F1];
__device__ float g_aggh[(size_t)NN * F1];
__device__ float g_logits[(size_t)NN * NC];

// ---------------- dtype detection + fused index conversion/degree ----------------
__global__ void k_detect(const unsigned int* __restrict__ ei32) {
    if (threadIdx.x == 0 && blockIdx.x == 0) {
        int all0 = 1;
        #pragma unroll 1
        for (int i = 0; i < 64; i++)
            if (ei32[2 * i + 1] != 0u) { all0 = 0; break; }
        g_e64 = all0;
    }
}

__device__ __forceinline__ int edge_idx(const void* ei, int half, int e) {
    if (g_e64) return (int)((const long long*)ei)[(size_t)half * NE + e];
    return ((const int*)ei)[(size_t)half * NE + e];
}

__global__ void k_deg_init() {
    int i = blockIdx.x * blockDim.x + threadIdx.x;
    if (i < NN) { g_dinv[i] = 1.0f; g_cursor[i] = 0; }
}

__global__ void k_convert_deg(const void* __restrict__ ei) {
    int e = blockIdx.x * blockDim.x + threadIdx.x;
    if (e < NE) {
        int s = edge_idx(ei, 0, e);
        int d = edge_idx(ei, 1, e);
        g_src32[e] = s;
        g_dst32[e] = d;
        atomicAdd(&g_dinv[d], 1.0f);
    }
}

// single-block scan of in-degrees -> g_rowptr  (indeg = deg - 1; deg exact in fp32)
__global__ void k_scan() {
    __shared__ int wsum[32];
    __shared__ int carry_s;
    const int tid = threadIdx.x, lane = tid & 31, wid = tid >> 5;
    if (tid == 0) { carry_s = 0; g_rowptr[0] = 0; }
    __syncthreads();
    for (int base = 0; base < NN; base += 1024) {
        int i = base + tid;
        int v = (i < NN) ? ((int)g_dinv[i] - 1) : 0;
        int x = v;
        #pragma unroll
        for (int o = 1; o < 32; o <<= 1) {
            int t = __shfl_up_sync(0xFFFFFFFFu, x, o);
            if (lane >= o) x += t;
        }
        if (lane == 31) wsum[wid] = x;
        __syncthreads();
        if (wid == 0) {
            int s = wsum[lane];
            #pragma unroll
            for (int o = 1; o < 32; o <<= 1) {
                int t = __shfl_up_sync(0xFFFFFFFFu, s, o);
                if (lane >= o) s += t;
            }
            wsum[lane] = s;
        }
        __syncthreads();
        int woff = (wid > 0) ? wsum[wid - 1] : 0;
        int incl = carry_s + woff + x;
        if (i < NN) g_rowptr[i + 1] = incl;
        __syncthreads();
        if (tid == 1023) carry_s = incl;
        __syncthreads();
    }
}

__global__ void k_dinv() {
    int i = blockIdx.x * blockDim.x + threadIdx.x;
    if (i < NN) g_dinv[i] = rsqrtf(g_dinv[i]);
}

__global__ void k_bucket() {
    int e = blockIdx.x * blockDim.x + threadIdx.x;
    if (e < NE) {
        int s = g_src32[e];
        int d = g_dst32[e];
        int pos = atomicAdd(&g_cursor[d], 1);
        float w = g_dinv[s] * g_dinv[d];
        g_epack[g_rowptr[d] + pos] = make_int2(s, __float_as_int(w));
    }
}

// ---------------- warp-per-node CSR gather: agg = self_norm*h[n] + sum norm*h[src] ----
// LAYER==1: h=x(param) F=128 (1 float4/lane). LAYER==2: h=g_l1 F=256 (2 float4/lane).
template <int LAYER>
__global__ void k_gather(const float* __restrict__ hparam) {
    const float* __restrict__ h = (LAYER == 1) ? hparam : g_l1;
    float* __restrict__ agg = (LAYER == 1) ? g_aggx : g_aggh;
    constexpr int F   = (LAYER == 1) ? F0 : F1;
    constexpr int NF4 = F / 128;

    const int warp = threadIdx.x >> 5;
    const int lane = threadIdx.x & 31;
    const int node = blockIdx.x * 8 + warp;
    if (node >= NN) return;

    float sn = g_dinv[node];
    sn *= sn;                                   // self_norm = 1/deg
    float4 acc[NF4];
    const float* hn = h + (size_t)node * F + lane * 4;
    #pragma unroll
    for (int i = 0; i < NF4; i++) {
        float4 v = *(const float4*)(hn + i * 128);
        acc[i] = make_float4(v.x * sn, v.y * sn, v.z * sn, v.w * sn);
    }

    const int s0 = g_rowptr[node];
    const int s1 = g_rowptr[node + 1];
    for (int j = s0; j < s1; j++) {
        int2 p = g_epack[j];                    // broadcast across warp
        float w = __int_as_float(p.y);
        const float* hs = h + (size_t)p.x * F + lane * 4;
        #pragma unroll
        for (int i = 0; i < NF4; i++) {
            float4 v = *(const float4*)(hs + i * 128);
            acc[i].x += w * v.x; acc[i].y += w * v.y;
            acc[i].z += w * v.z; acc[i].w += w * v.w;
        }
    }

    float* o = agg + (size_t)node * F + lane * 4;
    #pragma unroll
    for (int i = 0; i < NF4; i++)
        *(float4*)(o + i * 128) = acc[i];
}

// ---------------- bf16 split / mma helpers ----------------
__device__ __forceinline__ unsigned bf16pack(float e0, float e1) {
    unsigned r;
    asm("cvt.rn.bf16x2.f32 %0, %1, %2;" : "=r"(r) : "f"(e1), "f"(e0));
    return r;
}

__device__ __forceinline__ void bf16split(float e0, float e1, unsigned& h, unsigned& l) {
    h = bf16pack(e0, e1);
    float f0 = __uint_as_float(h << 16);
    float f1 = __uint_as_float(h & 0xFFFF0000u);
    l = bf16pack(e0 - f0, e1 - f1);
}

__device__ __forceinline__ void mma_bf16(float* d, const unsigned* a, const unsigned* b) {
    asm volatile(
        "mma.sync.aligned.m16n8k16.row.col.f32.bf16.bf16.f32 "
        "{%0,%1,%2,%3}, {%4,%5,%6,%7}, {%8,%9}, {%0,%1,%2,%3};"
        : "+f"(d[0]), "+f"(d[1]), "+f"(d[2]), "+f"(d[3])
        : "r"(a[0]), "r"(a[1]), "r"(a[2]), "r"(a[3]), "r"(b[0]), "r"(b[1]));
}

// ---------------- tensor-core GEMM (3xBF16 split, m16n8k16) — R13 form ----------------
// LAYER==1: g_l1 = relu(g_aggx @ W1 + b1).                     M=NN, N=F1, K=F0
// LAYER==2: relu(g_aggh @ W2 + b2) @ Wc -> atomic g_logits.    M=NN, N=F2, K=F1
template <int LAYER>
__global__ __launch_bounds__(256) void gemm_mma(const float* __restrict__ B,
                                                const float* __restrict__ bias,
                                                const float* __restrict__ Wc,
                                                int M, int N, int K) {
    const float* __restrict__ A = (LAYER == 1) ? g_aggx : g_aggh;

    constexpr int BM = 128, BN = 64, BK = 16;
    constexpr int ASTR = 12;
    constexpr int BSTR = 72;

    __shared__ __align__(16) unsigned As_h[BM][ASTR];
    __shared__ __align__(16) unsigned As_l[BM][ASTR];
    __shared__ __align__(16) unsigned Bs_h[BK / 2][BSTR];
    __shared__ __align__(16) unsigned Bs_l[BK / 2][BSTR];
    __shared__ float sWc[(LAYER == 2) ? BN * NC : 1];

    const int tid  = threadIdx.x;
    const int bm   = blockIdx.x * BM;
    const int bn   = blockIdx.y * BN;
    const int warp = tid >> 5;
    const int lane = tid & 31;
    const int wm   = (warp & 3) * 32;
    const int wn   = (warp >> 2) * 32;
    const int qr   = lane >> 2;
    const int qc   = lane & 3;

    const int ar  = tid >> 1;
    const int apc = (tid & 1) * 4;
    const int bpr = tid >> 5;
    const int bc0 = (tid & 31) * 2;
    const bool bcv = (bn + bc0) < N;

    if (LAYER == 2) {
        for (int i = tid; i < BN * NC; i += 256) {
            int row = bn + i / NC;
            sWc[i] = (row < F2) ? Wc[(size_t)row * NC + (i % NC)] : 0.f;
        }
    }

    float acc[2][4][4] = {};

    float4 pa0 = make_float4(0.f, 0.f, 0.f, 0.f);
    float4 pa1 = make_float4(0.f, 0.f, 0.f, 0.f);
    float2 pb0 = make_float2(0.f, 0.f);
    float2 pb1 = make_float2(0.f, 0.f);
    if (bm + ar < M) {
        const float* ap = A + (size_t)(bm + ar) * K + apc * 2;
        pa0 = *(const float4*)ap;
        pa1 = *(const float4*)(ap + 4);
    }
    if (bcv) {
        pb0 = *(const float2*)(B + (size_t)(2 * bpr    ) * N + bn + bc0);
        pb1 = *(const float2*)(B + (size_t)(2 * bpr + 1) * N + bn + bc0);
    }

    for (int k0 = 0; k0 < K; k0 += BK) {
        {
            unsigned h0, l0, h1, l1, h2, l2, h3, l3;
            bf16split(pa0.x, pa0.y, h0, l0);
            bf16split(pa0.z, pa0.w, h1, l1);
            bf16split(pa1.x, pa1.y, h2, l2);
            bf16split(pa1.z, pa1.w, h3, l3);
            *(uint4*)&As_h[ar][apc] = make_uint4(h0, h1, h2, h3);
            *(uint4*)&As_l[ar][apc] = make_uint4(l0, l1, l2, l3);

            unsigned bh0, bl0, bh1, bl1;
            bf16split(pb0.x, pb1.x, bh0, bl0);
            bf16split(pb0.y, pb1.y, bh1, bl1);
            Bs_h[bpr][bc0]     = bh0;
            Bs_h[bpr][bc0 + 1] = bh1;
            Bs_l[bpr][bc0]     = bl0;
            Bs_l[bpr][bc0 + 1] = bl1;
        }
        __syncthreads();

        const int kn = k0 + BK;
        if (kn < K) {
            if (bm + ar < M) {
                const float* ap = A + (size_t)(bm + ar) * K + kn + apc * 2;
                pa0 = *(const float4*)ap;
                pa1 = *(const float4*)(ap + 4);
            }
            if (bcv) {
                pb0 = *(const float2*)(B + (size_t)(kn + 2 * bpr    ) * N + bn + bc0);
                pb1 = *(const float2*)(B + (size_t)(kn + 2 * bpr + 1) * N + bn + bc0);
            }
        }

        unsigned ah[2][4], al[2][4];
        #pragma unroll
        for (int mt = 0; mt < 2; mt++) {
            const int rb = wm + mt * 16;
            ah[mt][0] = As_h[rb + qr    ][qc    ];
            ah[mt][1] = As_h[rb + qr + 8][qc    ];
            ah[mt][2] = As_h[rb + qr    ][qc + 4];
            ah[mt][3] = As_h[rb + qr + 8][qc + 4];
            al[mt][0] = As_l[rb + qr    ][qc    ];
            al[mt][1] = As_l[rb + qr + 8][qc    ];
            al[mt][2] = As_l[rb + qr    ][qc + 4];
            al[mt][3] = As_l[rb + qr + 8][qc + 4];
        }
        unsigned bh[4][2], bl[4][2];
        #pragma unroll
        for (int nt = 0; nt < 4; nt++) {
            const int col = wn + nt * 8 + qr;
            bh[nt][0] = Bs_h[qc    ][col];
            bh[nt][1] = Bs_h[qc + 4][col];
            bl[nt][0] = Bs_l[qc    ][col];
            bl[nt][1] = Bs_l[qc + 4][col];
        }
        #pragma unroll
        for (int mt = 0; mt < 2; mt++)
            #pragma unroll
            for (int nt = 0; nt < 4; nt++) {
                mma_bf16(acc[mt][nt], ah[mt], bh[nt]);
                mma_bf16(acc[mt][nt], ah[mt], bl[nt]);
                mma_bf16(acc[mt][nt], al[mt], bh[nt]);
            }
        __syncthreads();
    }

    if (LAYER == 1) {
        #pragma unroll
        for (int mt = 0; mt < 2; mt++) {
            const int r0 = bm + wm + mt * 16 + qr;
            #pragma unroll
            for (int nt = 0; nt < 4; nt++) {
                const int col = bn + wn + nt * 8 + qc * 2;
                if (col < N) {
                    float2 bv = *(const float2*)(bias + col);
                    float v0 = fmaxf(acc[mt][nt][0] + bv.x, 0.f);
                    float v1 = fmaxf(acc[mt][nt][1] + bv.y, 0.f);
                    float v2 = fmaxf(acc[mt][nt][2] + bv.x, 0.f);
                    float v3 = fmaxf(acc[mt][nt][3] + bv.y, 0.f);
                    if (r0 < M)
                        *(float2*)(g_l1 + (size_t)r0 * N + col) = make_float2(v0, v1);
                    if (r0 + 8 < M)
                        *(float2*)(g_l1 + (size_t)(r0 + 8) * N + col) = make_float2(v2, v3);
                }
            }
        }
    } else {
        float plog[4][NC];
        #pragma unroll
        for (int r = 0; r < 4; r++)
            #pragma unroll
            for (int c = 0; c < NC; c++) plog[r][c] = 0.f;

        #pragma unroll
        for (int mt = 0; mt < 2; mt++) {
            #pragma unroll
            for (int nt = 0; nt < 4; nt++) {
                const int col = bn + wn + nt * 8 + qc * 2;
                if (col < N) {
                    float2 bv = *(const float2*)(bias + col);
                    float v0 = fmaxf(acc[mt][nt][0] + bv.x, 0.f);
                    float v1 = fmaxf(acc[mt][nt][1] + bv.y, 0.f);
                    float v2 = fmaxf(acc[mt][nt][2] + bv.x, 0.f);
                    float v3 = fmaxf(acc[mt][nt][3] + bv.y, 0.f);
                    const float* w0 = &sWc[(col - bn) * NC];
                    const float* w1 = w0 + NC;
                    #pragma unroll
                    for (int c = 0; c < NC; c++) {
                        plog[mt * 2 + 0][c] += v0 * w0[c] + v1 * w1[c];
                        plog[mt * 2 + 1][c] += v2 * w0[c] + v3 * w1[c];
                    }
                }
            }
        }
        #pragma unroll
        for (int off = 1; off <= 2; off <<= 1)
            #pragma unroll
            for (int r = 0; r < 4; r++)
                #pragma unroll
                for (int c = 0; c < NC; c++)
                    plog[r][c] += __shfl_xor_sync(0xFFFFFFFFu, plog[r][c], off);

        if (qc == 0) {
            #pragma unroll
            for (int mt = 0; mt < 2; mt++) {
                const int r0 = bm + wm + mt * 16 + qr;
                if (r0 < M)
                    #pragma unroll
                    for (int c = 0; c < NC; c++)
                        atomicAdd(&g_logits[(size_t)r0 * NC + c], plog[mt * 2][c]);
                if (r0 + 8 < M)
                    #pragma unroll
                    for (int c = 0; c < NC; c++)
                        atomicAdd(&g_logits[(size_t)(r0 + 8) * NC + c], plog[mt * 2 + 1][c]);
            }
        }
    }
}

// ---------------- logits init (bc) + final log_softmax ----------------
__global__ void k_logits_init(const float* __restrict__ bc) {
    int i = blockIdx.x * blockDim.x + threadIdx.x;
    if (i < NN * NC) g_logits[i] = bc[i % NC];
}

__global__ void k_logsoftmax(float* __restrict__ out) {
    int n = blockIdx.x * blockDim.x + threadIdx.x;
    if (n >= NN) return;
    float l[NC];
    float m = -1e30f;
    #pragma unroll
    for (int c = 0; c < NC; c++) {
        l[c] = g_logits[(size_t)n * NC + c];
        m = fmaxf(m, l[c]);
    }
    float s = 0.f;
    #pragma unroll
    for (int c = 0; c < NC; c++) s += expf(l[c] - m);
    float ls = m + logf(s);
    #pragma unroll
    for (int c = 0; c < NC; c++)
        out[(size_t)n * NC + c] = l[c] - ls;
}

// ---------------- launch ----------------
extern "C" void kernel_launch(void* const* d_in, const int* in_sizes, int n_in,
                              void* d_out, int out_size) {
    const float* x   = (const float*)d_in[0];
    const void*  ei  = d_in[1];
    const float* W1  = (const float*)d_in[2];
    const float* b1  = (const float*)d_in[3];
    const float* W2  = (const float*)d_in[4];
    const float* b2  = (const float*)d_in[5];
    const float* Wc  = (const float*)d_in[6];
    const float* bc  = (const float*)d_in[7];
    float*       out = (float*)d_out;

    const int T = 256;

    // CSR build: detect -> deg -> scan -> dinv -> bucket
    k_detect<<<1, 32>>>((const unsigned int*)ei);
    k_deg_init<<<(NN + T - 1) / T, T>>>();
    k_convert_deg<<<(NE + T - 1) / T, T>>>(ei);
    k_scan<<<1, 1024>>>();
    k_dinv<<<(NN + T - 1) / T, T>>>();
    k_bucket<<<(NE + T - 1) / T, T>>>();

    // aggx = S x (atomic-free gather)
    k_gather<1><<<(NN + 7) / 8, 256>>>(x);

    // l1 = relu(aggx @ W1 + b1)
    gemm_mma<1><<<dim3((NN + 127) / 128, (F1 + 63) / 64), T>>>(W1, b1, nullptr, NN, F1, F0);

    // aggh = S l1 (atomic-free gather)
    k_gather<2><<<(NN + 7) / 8, 256>>>(nullptr);

    // logits = bc; GEMM2 accumulates relu(aggh@W2+b2)@Wc atomically
    k_logits_init<<<(NN * NC + T - 1) / T, T>>>(bc);
    gemm_mma<2><<<dim3((NN + 127) / 128, (F2 + 63) / 64), T>>>(W2, b2, Wc, NN, F2, F1);

    k_logsoftmax<<<(NN + T - 1) / T, T>>>(out);
}